// round 1
// baseline (speedup 1.0000x reference)
#include <cuda_runtime.h>
#include <math.h>

// Problem constants
#define SEQ   2048
#define BATCH 2
#define DMODEL 1024
#define NHEAD 16
#define DHEAD 64
#define NROWS (BATCH * SEQ)          // 4096
#define OUT_ELEMS   (NROWS * DMODEL)             // 4,194,304
#define ATTN_ELEMS  (BATCH * NHEAD * SEQ * SEQ)  // 134,217,728

// -------------------- device scratch (no allocations allowed) ------------
__device__ float g_q[NROWS * DMODEL];
__device__ float g_k[NROWS * DMODEL];
__device__ float g_v[NROWS * DMODEL];
__device__ float g_ctx[NROWS * DMODEL];
__device__ float g_o[NROWS * DMODEL];
__device__ float g_rowsum[BATCH * NHEAD * SEQ];

__device__ __forceinline__ float* buf_sel(int s) {
    switch (s) {
        case 0: return g_q;
        case 1: return g_k;
        case 2: return g_v;
        case 3: return g_ctx;
        default: return g_o;
    }
}

// -------------------- SGEMM: C[4096,1024] = A @ W + bias ------------------
// BM=BN=128, BK=8, 256 threads, 8x8 per-thread tile.
__global__ __launch_bounds__(256)
void sgemm_bias(const float* __restrict__ A_ext, int a_sel,
                const float* __restrict__ W, const float* __restrict__ bias,
                int c_sel) {
    __shared__ float As[8][128];
    __shared__ float Bs[8][128];

    const float* A = A_ext ? A_ext : buf_sel(a_sel);
    float* C = buf_sel(c_sel);

    const int tid = threadIdx.x;
    const int bm = blockIdx.y * 128;
    const int bn = blockIdx.x * 128;
    const int ty = tid >> 4, tx = tid & 15;

    const int arow = tid >> 1, acol = (tid & 1) << 2;     // A: 128 rows x 8 k
    const int wrow = tid >> 5, wcol = (tid & 31) << 2;    // W: 8 k x 128 n

    float acc[8][8];
#pragma unroll
    for (int i = 0; i < 8; ++i)
#pragma unroll
        for (int j = 0; j < 8; ++j) acc[i][j] = 0.0f;

    const float* Ap = A + (size_t)(bm + arow) * DMODEL + acol;
    const float* Wp = W + (size_t)wrow * DMODEL + bn + wcol;

    for (int k0 = 0; k0 < DMODEL; k0 += 8) {
        float4 av = *(const float4*)(Ap + k0);
        As[acol + 0][arow] = av.x;
        As[acol + 1][arow] = av.y;
        As[acol + 2][arow] = av.z;
        As[acol + 3][arow] = av.w;
        *(float4*)&Bs[wrow][wcol] = *(const float4*)(Wp + (size_t)k0 * DMODEL);
        __syncthreads();
#pragma unroll
        for (int kk = 0; kk < 8; ++kk) {
            float ar[8], br[8];
            *(float4*)&ar[0] = *(float4*)&As[kk][ty * 8];
            *(float4*)&ar[4] = *(float4*)&As[kk][ty * 8 + 4];
            *(float4*)&br[0] = *(float4*)&Bs[kk][tx * 8];
            *(float4*)&br[4] = *(float4*)&Bs[kk][tx * 8 + 4];
#pragma unroll
            for (int i = 0; i < 8; ++i)
#pragma unroll
                for (int j = 0; j < 8; ++j)
                    acc[i][j] = fmaf(ar[i], br[j], acc[i][j]);
        }
        __syncthreads();
    }

#pragma unroll
    for (int i = 0; i < 8; ++i) {
        float* Cp = C + (size_t)(bm + ty * 8 + i) * DMODEL + bn + tx * 8;
#pragma unroll
        for (int j = 0; j < 8; j += 4) {
            float4 o;
            o.x = acc[i][j + 0] + bias[bn + tx * 8 + j + 0];
            o.y = acc[i][j + 1] + bias[bn + tx * 8 + j + 1];
            o.z = acc[i][j + 2] + bias[bn + tx * 8 + j + 2];
            o.w = acc[i][j + 3] + bias[bn + tx * 8 + j + 3];
            *(float4*)(Cp + j) = o;
        }
    }
}

// -------------------- fused attention ------------------------------------
// Block: 64 q-rows of one (b,h). Streams K/V in 64-key chunks.
// Writes UNNORMALIZED exp(logits) to gattn; ctx normalized in-kernel.
#define LDP 68
#define ATTN_SMEM_BYTES ((4 * DHEAD * LDP + 64) * (int)sizeof(float))

__global__ __launch_bounds__(256)
void attn_kernel(float* __restrict__ gattn) {
    extern __shared__ float sm[];
    float* Qs = sm;                  // [d][q]   64x68
    float* Ks = Qs + DHEAD * LDP;    // [d][key] 64x68
    float* Vs = Ks + DHEAD * LDP;    // [key][d] 64x68
    float* Es = Vs + DHEAD * LDP;    // [q][key] 64x68
    float* rs = Es + 64 * LDP;       // [64]

    const int tid = threadIdx.x;
    const int q0 = blockIdx.x * 64;
    const int h = blockIdx.y;
    const int b = blockIdx.z;
    const int ty = tid >> 4, tx = tid & 15;

    const float* qbase = g_q + (size_t)b * SEQ * DMODEL + h * DHEAD;
    const float* kbase = g_k + (size_t)b * SEQ * DMODEL + h * DHEAD;
    const float* vbase = g_v + (size_t)b * SEQ * DMODEL + h * DHEAD;

    // Load Q tile transposed: Qs[d][q]
    {
        const int qi = tid & 63;
        const int d0 = tid >> 6;   // 0..3
#pragma unroll
        for (int it = 0; it < 4; ++it) {
            int d4 = d0 + it * 4;  // 0..15
            float4 v = *(const float4*)(qbase + (size_t)(q0 + qi) * DMODEL + d4 * 4);
            Qs[(d4 * 4 + 0) * LDP + qi] = v.x;
            Qs[(d4 * 4 + 1) * LDP + qi] = v.y;
            Qs[(d4 * 4 + 2) * LDP + qi] = v.z;
            Qs[(d4 * 4 + 3) * LDP + qi] = v.w;
        }
    }

    float acc[4][4];
#pragma unroll
    for (int i = 0; i < 4; ++i)
#pragma unroll
        for (int j = 0; j < 4; ++j) acc[i][j] = 0.0f;
    float psum[4] = {0.f, 0.f, 0.f, 0.f};

    for (int kc = 0; kc < SEQ; kc += 64) {
        __syncthreads();  // guards Qs fill (1st iter) and Es/Vs readers (later iters)
        // Load K chunk transposed: Ks[d][key]; V chunk natural: Vs[key][d]
        {
            const int ki = tid & 63;
            const int d0 = tid >> 6;
#pragma unroll
            for (int it = 0; it < 4; ++it) {
                int d4 = d0 + it * 4;
                float4 v = *(const float4*)(kbase + (size_t)(kc + ki) * DMODEL + d4 * 4);
                Ks[(d4 * 4 + 0) * LDP + ki] = v.x;
                Ks[(d4 * 4 + 1) * LDP + ki] = v.y;
                Ks[(d4 * 4 + 2) * LDP + ki] = v.z;
                Ks[(d4 * 4 + 3) * LDP + ki] = v.w;
            }
#pragma unroll
            for (int it = 0; it < 4; ++it) {
                int idx = tid + 256 * it;
                int key = idx >> 4;
                int d4 = idx & 15;
                *(float4*)&Vs[key * LDP + d4 * 4] =
                    *(const float4*)(vbase + (size_t)(kc + key) * DMODEL + d4 * 4);
            }
        }
        __syncthreads();

        // logits tile 64x64 -> exp
        float e[4][4];
        {
            float lt[4][4];
#pragma unroll
            for (int i = 0; i < 4; ++i)
#pragma unroll
                for (int j = 0; j < 4; ++j) lt[i][j] = 0.0f;
#pragma unroll 16
            for (int kk = 0; kk < DHEAD; ++kk) {
                float4 a = *(float4*)&Qs[kk * LDP + ty * 4];
                float4 bb = *(float4*)&Ks[kk * LDP + tx * 4];
                float av[4] = {a.x, a.y, a.z, a.w};
                float bv[4] = {bb.x, bb.y, bb.z, bb.w};
#pragma unroll
                for (int i = 0; i < 4; ++i)
#pragma unroll
                    for (int j = 0; j < 4; ++j)
                        lt[i][j] = fmaf(av[i], bv[j], lt[i][j]);
            }
#pragma unroll
            for (int i = 0; i < 4; ++i)
#pragma unroll
                for (int j = 0; j < 4; ++j)
                    e[i][j] = __expf(lt[i][j] * 0.125f);
        }
#pragma unroll
        for (int i = 0; i < 4; ++i) {
            float4 ev = make_float4(e[i][0], e[i][1], e[i][2], e[i][3]);
            *(float4*)&Es[(ty * 4 + i) * LDP + tx * 4] = ev;
            psum[i] += (e[i][0] + e[i][1]) + (e[i][2] + e[i][3]);
            if (gattn) {
                size_t row = (size_t)((b * NHEAD + h) * SEQ + q0 + ty * 4 + i);
                *(float4*)&gattn[row * SEQ + kc + tx * 4] = ev;
            }
        }
        __syncthreads();

        // ctx += Es @ Vs
#pragma unroll 16
        for (int kk = 0; kk < 64; ++kk) {
            float4 vv = *(float4*)&Vs[kk * LDP + tx * 4];
#pragma unroll
            for (int i = 0; i < 4; ++i) {
                float p = Es[(ty * 4 + i) * LDP + kk];
                acc[i][0] = fmaf(p, vv.x, acc[i][0]);
                acc[i][1] = fmaf(p, vv.y, acc[i][1]);
                acc[i][2] = fmaf(p, vv.z, acc[i][2]);
                acc[i][3] = fmaf(p, vv.w, acc[i][3]);
            }
        }
    }

    // reduce rowsum across the 16 tx-lanes of each row group
#pragma unroll
    for (int i = 0; i < 4; ++i) {
        psum[i] += __shfl_xor_sync(0xffffffffu, psum[i], 8);
        psum[i] += __shfl_xor_sync(0xffffffffu, psum[i], 4);
        psum[i] += __shfl_xor_sync(0xffffffffu, psum[i], 2);
        psum[i] += __shfl_xor_sync(0xffffffffu, psum[i], 1);
    }
    if (tx == 0) {
#pragma unroll
        for (int i = 0; i < 4; ++i)
            g_rowsum[(size_t)(b * NHEAD + h) * SEQ + q0 + ty * 4 + i] = psum[i];
    }
    (void)rs;

    // normalize and write ctx into [b, s, h*64+d] layout
#pragma unroll
    for (int i = 0; i < 4; ++i) {
        float inv = 1.0f / psum[i];
        float4 o = make_float4(acc[i][0] * inv, acc[i][1] * inv,
                               acc[i][2] * inv, acc[i][3] * inv);
        *(float4*)&g_ctx[(size_t)(b * SEQ + q0 + ty * 4 + i) * DMODEL + h * DHEAD + tx * 4] = o;
    }
}

// -------------------- attn rescale: p = e / rowsum ------------------------
__global__ __launch_bounds__(256)
void attn_scale(float* __restrict__ attn) {
    size_t i = (size_t)blockIdx.x * 256 + threadIdx.x;   // float4 index
    size_t row = i >> 9;                                 // 512 float4 per row
    float inv = 1.0f / g_rowsum[row];
    float4* p = (float4*)attn;
    float4 v = p[i];
    v.x *= inv; v.y *= inv; v.z *= inv; v.w *= inv;
    p[i] = v;
}

// -------------------- LayerNorm ------------------------------------------
__global__ __launch_bounds__(256)
void ln_kernel(const float* __restrict__ gamma, const float* __restrict__ beta,
               float* __restrict__ out) {
    const int row = blockIdx.x;
    const int tid = threadIdx.x;
    __shared__ float red[8];

    float4 x = *(const float4*)&g_o[(size_t)row * DMODEL + tid * 4];
    float s = (x.x + x.y) + (x.z + x.w);
#pragma unroll
    for (int off = 16; off; off >>= 1) s += __shfl_xor_sync(0xffffffffu, s, off);
    if ((tid & 31) == 0) red[tid >> 5] = s;
    __syncthreads();
    float tot = 0.f;
#pragma unroll
    for (int i = 0; i < 8; ++i) tot += red[i];
    float mean = tot * (1.0f / 1024.0f);
    __syncthreads();

    float4 dx = make_float4(x.x - mean, x.y - mean, x.z - mean, x.w - mean);
    float ss = dx.x * dx.x + dx.y * dx.y + dx.z * dx.z + dx.w * dx.w;
#pragma unroll
    for (int off = 16; off; off >>= 1) ss += __shfl_xor_sync(0xffffffffu, ss, off);
    if ((tid & 31) == 0) red[tid >> 5] = ss;
    __syncthreads();
    float tss = 0.f;
#pragma unroll
    for (int i = 0; i < 8; ++i) tss += red[i];
    float var = tss * (1.0f / 1024.0f);
    float rstd = rsqrtf(var + 1e-3f);

    float4 g = *(const float4*)&gamma[tid * 4];
    float4 be = *(const float4*)&beta[tid * 4];
    float4 o;
    o.x = dx.x * rstd * g.x + be.x;
    o.y = dx.y * rstd * g.y + be.y;
    o.z = dx.z * rstd * g.z + be.z;
    o.w = dx.w * rstd * g.w + be.w;
    *(float4*)&out[(size_t)row * DMODEL + tid * 4] = o;
}

// -------------------- launcher --------------------------------------------
extern "C" void kernel_launch(void* const* d_in, const int* in_sizes, int n_in,
                              void* d_out, int out_size) {
    const float* query = (const float*)d_in[0];
    const float* key   = (const float*)d_in[1];
    const float* value = (const float*)d_in[2];
    const float* Wq = (const float*)d_in[3];
    const float* bq = (const float*)d_in[4];
    const float* Wk = (const float*)d_in[5];
    const float* bk = (const float*)d_in[6];
    const float* Wv = (const float*)d_in[7];
    const float* bv = (const float*)d_in[8];
    const float* Wo = (const float*)d_in[9];
    const float* bo = (const float*)d_in[10];
    const float* gamma = (const float*)d_in[11];
    const float* beta  = (const float*)d_in[12];

    float* out = (float*)d_out;
    float* attn = (out_size >= OUT_ELEMS + ATTN_ELEMS) ? (out + OUT_ELEMS) : nullptr;

    cudaFuncSetAttribute(attn_kernel, cudaFuncAttributeMaxDynamicSharedMemorySize,
                         ATTN_SMEM_BYTES);

    dim3 gproj(DMODEL / 128, NROWS / 128);   // (8, 32)
    sgemm_bias<<<gproj, 256>>>(query, -1, Wq, bq, 0);
    sgemm_bias<<<gproj, 256>>>(key,   -1, Wk, bk, 1);
    sgemm_bias<<<gproj, 256>>>(value, -1, Wv, bv, 2);

    attn_kernel<<<dim3(SEQ / 64, NHEAD, BATCH), 256, ATTN_SMEM_BYTES>>>(attn);

    if (attn) {
        attn_scale<<<ATTN_ELEMS / 4 / 256, 256>>>(attn);
    }

    sgemm_bias<<<gproj, 256>>>(nullptr, 3, Wo, bo, 4);   // g_ctx @ Wo -> g_o
    ln_kernel<<<NROWS, 256>>>(gamma, beta, out);
}

// round 3
// speedup vs baseline: 1.2880x; 1.2880x over previous
#include <cuda_runtime.h>
#include <cuda_bf16.h>
#include <math.h>
#include <stdint.h>

// Problem constants
#define SEQ   2048
#define BATCH 2
#define DMODEL 1024
#define NHEAD 16
#define DHEAD 64
#define NROWS (BATCH * SEQ)          // 4096
#define OUT_ELEMS   (NROWS * DMODEL)             // 4,194,304
#define ATTN_ELEMS  (BATCH * NHEAD * SEQ * SEQ)  // 134,217,728

// -------------------- device scratch (no allocations allowed) ------------
__device__ float g_q[NROWS * DMODEL];
__device__ float g_k[NROWS * DMODEL];
__device__ float g_v[NROWS * DMODEL];
__device__ float g_ctx[NROWS * DMODEL];
__device__ float g_o[NROWS * DMODEL];
__device__ float g_rowsum[BATCH * NHEAD * SEQ];

__device__ __forceinline__ float* buf_sel(int s) {
    switch (s) {
        case 0: return g_q;
        case 1: return g_k;
        case 2: return g_v;
        case 3: return g_ctx;
        default: return g_o;
    }
}

// ==================== tensor-core projection GEMM =========================
// C[4096,1024] = A(fp32) @ W(fp32) + bias, via split-bf16 (hi+lo) mma.sync.
// BM=BN=128, BK=32, 256 threads = 8 warps (4x2), warp tile 32x64.
// Accuracy: hi*hi + hi*lo + lo*hi, error ~1e-5 rel.

__device__ __forceinline__ void ldsm_x4(uint32_t (&r)[4], uint32_t addr) {
    asm volatile("ldmatrix.sync.aligned.m8n8.x4.shared.b16 {%0,%1,%2,%3}, [%4];"
                 : "=r"(r[0]), "=r"(r[1]), "=r"(r[2]), "=r"(r[3]) : "r"(addr));
}
__device__ __forceinline__ void ldsm_x4_t(uint32_t (&r)[4], uint32_t addr) {
    asm volatile("ldmatrix.sync.aligned.m8n8.x4.trans.shared.b16 {%0,%1,%2,%3}, [%4];"
                 : "=r"(r[0]), "=r"(r[1]), "=r"(r[2]), "=r"(r[3]) : "r"(addr));
}
__device__ __forceinline__ void mma16816(float (&c)[4], const uint32_t (&a)[4],
                                         uint32_t b0, uint32_t b1) {
    asm volatile(
        "mma.sync.aligned.m16n8k16.row.col.f32.bf16.bf16.f32 "
        "{%0,%1,%2,%3}, {%4,%5,%6,%7}, {%8,%9}, {%0,%1,%2,%3};"
        : "+f"(c[0]), "+f"(c[1]), "+f"(c[2]), "+f"(c[3])
        : "r"(a[0]), "r"(a[1]), "r"(a[2]), "r"(a[3]), "r"(b0), "r"(b1));
}

__device__ __forceinline__ uint32_t pack_hi(float x, float y) {
    __nv_bfloat162 h = __floats2bfloat162_rn(x, y);
    return *(uint32_t*)&h;
}

#define A_LD 40   // 32 + 8 pad (bf16 units); row stride 80B (mult of 16)
#define B_LD 136  // 128 + 8 pad;            row stride 272B (mult of 16)

__global__ __launch_bounds__(256)
void gemm_tc(const float* __restrict__ A_ext, int a_sel,
             const float* __restrict__ W, const float* __restrict__ bias,
             int c_sel) {
    __shared__ __nv_bfloat16 Ah[128][A_LD];
    __shared__ __nv_bfloat16 Al[128][A_LD];
    __shared__ __nv_bfloat16 Bh[32][B_LD];
    __shared__ __nv_bfloat16 Bl[32][B_LD];

    const float* A = A_ext ? A_ext : buf_sel(a_sel);
    float* C = buf_sel(c_sel);

    const int tid = threadIdx.x;
    const int lane = tid & 31;
    const int warp = tid >> 5;
    const int wm = (warp & 3) * 32;   // warp row offset in tile
    const int wn = (warp >> 2) * 64;  // warp col offset in tile
    const int bm = blockIdx.y * 128;
    const int bn = blockIdx.x * 128;

    // gmem load coords
    const int a_row = tid >> 1;                 // 0..127
    const int a_col0 = (tid & 1) * 16;          // 0 or 16
    const int b_row = tid >> 3;                 // 0..31
    const int b_col0 = (tid & 7) * 16;          // 0..112

    float acc[2][8][4];
#pragma unroll
    for (int i = 0; i < 2; ++i)
#pragma unroll
        for (int j = 0; j < 8; ++j)
#pragma unroll
            for (int r = 0; r < 4; ++r) acc[i][j][r] = 0.f;

    const int lr = lane & 15;
    const int lh = lane >> 4;

    for (int k0 = 0; k0 < DMODEL; k0 += 32) {
        // ---- fill smem with split-bf16 ----
#pragma unroll
        for (int i = 0; i < 4; ++i) {
            const float* src = A + (size_t)(bm + a_row) * DMODEL + k0 + a_col0 + i * 4;
            float4 v = *(const float4*)src;
            float hx = __bfloat162float(__float2bfloat16_rn(v.x));
            float hy = __bfloat162float(__float2bfloat16_rn(v.y));
            float hz = __bfloat162float(__float2bfloat16_rn(v.z));
            float hw = __bfloat162float(__float2bfloat16_rn(v.w));
            int c = a_col0 + i * 4;
            *(uint32_t*)&Ah[a_row][c]     = pack_hi(v.x, v.y);
            *(uint32_t*)&Ah[a_row][c + 2] = pack_hi(v.z, v.w);
            *(uint32_t*)&Al[a_row][c]     = pack_hi(v.x - hx, v.y - hy);
            *(uint32_t*)&Al[a_row][c + 2] = pack_hi(v.z - hz, v.w - hw);
        }
#pragma unroll
        for (int i = 0; i < 4; ++i) {
            const float* src = W + (size_t)(k0 + b_row) * DMODEL + bn + b_col0 + i * 4;
            float4 v = *(const float4*)src;
            float hx = __bfloat162float(__float2bfloat16_rn(v.x));
            float hy = __bfloat162float(__float2bfloat16_rn(v.y));
            float hz = __bfloat162float(__float2bfloat16_rn(v.z));
            float hw = __bfloat162float(__float2bfloat16_rn(v.w));
            int c = b_col0 + i * 4;
            *(uint32_t*)&Bh[b_row][c]     = pack_hi(v.x, v.y);
            *(uint32_t*)&Bh[b_row][c + 2] = pack_hi(v.z, v.w);
            *(uint32_t*)&Bl[b_row][c]     = pack_hi(v.x - hx, v.y - hy);
            *(uint32_t*)&Bl[b_row][c + 2] = pack_hi(v.z - hz, v.w - hw);
        }
        __syncthreads();

        // ---- compute 2 k-steps of 16 ----
#pragma unroll
        for (int ks = 0; ks < 2; ++ks) {
            uint32_t afh[2][4], afl[2][4];
#pragma unroll
            for (int mt = 0; mt < 2; ++mt) {
                uint32_t adrh = (uint32_t)__cvta_generic_to_shared(
                    &Ah[wm + mt * 16 + lr][ks * 16 + lh * 8]);
                uint32_t adrl = (uint32_t)__cvta_generic_to_shared(
                    &Al[wm + mt * 16 + lr][ks * 16 + lh * 8]);
                ldsm_x4(afh[mt], adrh);
                ldsm_x4(afl[mt], adrl);
            }
#pragma unroll
            for (int np = 0; np < 4; ++np) {   // n-tile pair (2 tiles of 8)
                // B frag: rows k = ks*16 + lane%16 ; cols n = wn + np*16 + (lane/16)*8
                uint32_t badr_h = (uint32_t)__cvta_generic_to_shared(
                    &Bh[ks * 16 + lr][wn + np * 16 + lh * 8]);
                uint32_t badr_l = (uint32_t)__cvta_generic_to_shared(
                    &Bl[ks * 16 + lr][wn + np * 16 + lh * 8]);
                uint32_t bfh[4], bfl[4];
                ldsm_x4_t(bfh, badr_h);
                ldsm_x4_t(bfl, badr_l);
#pragma unroll
                for (int mt = 0; mt < 2; ++mt) {
                    mma16816(acc[mt][2 * np],     afh[mt], bfh[0], bfh[1]);
                    mma16816(acc[mt][2 * np],     afh[mt], bfl[0], bfl[1]);
                    mma16816(acc[mt][2 * np],     afl[mt], bfh[0], bfh[1]);
                    mma16816(acc[mt][2 * np + 1], afh[mt], bfh[2], bfh[3]);
                    mma16816(acc[mt][2 * np + 1], afh[mt], bfl[2], bfl[3]);
                    mma16816(acc[mt][2 * np + 1], afl[mt], bfh[2], bfh[3]);
                }
            }
        }
        __syncthreads();
    }

    // ---- epilogue: bias + store ----
    const int gid = lane >> 2;   // 0..7
    const int qid = lane & 3;    // 0..3
#pragma unroll
    for (int mt = 0; mt < 2; ++mt) {
#pragma unroll
        for (int nt = 0; nt < 8; ++nt) {
            int col = bn + wn + nt * 8 + qid * 2;
            float b0 = bias[col], b1 = bias[col + 1];
            int r0 = bm + wm + mt * 16 + gid;
            float2 v0 = make_float2(acc[mt][nt][0] + b0, acc[mt][nt][1] + b1);
            float2 v1 = make_float2(acc[mt][nt][2] + b0, acc[mt][nt][3] + b1);
            *(float2*)&C[(size_t)r0 * DMODEL + col] = v0;
            *(float2*)&C[(size_t)(r0 + 8) * DMODEL + col] = v1;
        }
    }
}

// -------------------- fused attention (fp32, unchanged from R1) ----------
#define LDP 68
#define ATTN_SMEM_BYTES ((4 * DHEAD * LDP + 64) * (int)sizeof(float))

__global__ __launch_bounds__(256)
void attn_kernel(float* __restrict__ gattn) {
    extern __shared__ float sm[];
    float* Qs = sm;                  // [d][q]   64x68
    float* Ks = Qs + DHEAD * LDP;    // [d][key] 64x68
    float* Vs = Ks + DHEAD * LDP;    // [key][d] 64x68
    float* Es = Vs + DHEAD * LDP;    // [q][key] 64x68

    const int tid = threadIdx.x;
    const int q0 = blockIdx.x * 64;
    const int h = blockIdx.y;
    const int b = blockIdx.z;
    const int ty = tid >> 4, tx = tid & 15;

    const float* qbase = g_q + (size_t)b * SEQ * DMODEL + h * DHEAD;
    const float* kbase = g_k + (size_t)b * SEQ * DMODEL + h * DHEAD;
    const float* vbase = g_v + (size_t)b * SEQ * DMODEL + h * DHEAD;

    {
        const int qi = tid & 63;
        const int d0 = tid >> 6;
#pragma unroll
        for (int it = 0; it < 4; ++it) {
            int d4 = d0 + it * 4;
            float4 v = *(const float4*)(qbase + (size_t)(q0 + qi) * DMODEL + d4 * 4);
            Qs[(d4 * 4 + 0) * LDP + qi] = v.x;
            Qs[(d4 * 4 + 1) * LDP + qi] = v.y;
            Qs[(d4 * 4 + 2) * LDP + qi] = v.z;
            Qs[(d4 * 4 + 3) * LDP + qi] = v.w;
        }
    }

    float acc[4][4];
#pragma unroll
    for (int i = 0; i < 4; ++i)
#pragma unroll
        for (int j = 0; j < 4; ++j) acc[i][j] = 0.0f;
    float psum[4] = {0.f, 0.f, 0.f, 0.f};

    for (int kc = 0; kc < SEQ; kc += 64) {
        __syncthreads();
        {
            const int ki = tid & 63;
            const int d0 = tid >> 6;
#pragma unroll
            for (int it = 0; it < 4; ++it) {
                int d4 = d0 + it * 4;
                float4 v = *(const float4*)(kbase + (size_t)(kc + ki) * DMODEL + d4 * 4);
                Ks[(d4 * 4 + 0) * LDP + ki] = v.x;
                Ks[(d4 * 4 + 1) * LDP + ki] = v.y;
                Ks[(d4 * 4 + 2) * LDP + ki] = v.z;
                Ks[(d4 * 4 + 3) * LDP + ki] = v.w;
            }
#pragma unroll
            for (int it = 0; it < 4; ++it) {
                int idx = tid + 256 * it;
                int key = idx >> 4;
                int d4 = idx & 15;
                *(float4*)&Vs[key * LDP + d4 * 4] =
                    *(const float4*)(vbase + (size_t)(kc + key) * DMODEL + d4 * 4);
            }
        }
        __syncthreads();

        float e[4][4];
        {
            float lt[4][4];
#pragma unroll
            for (int i = 0; i < 4; ++i)
#pragma unroll
                for (int j = 0; j < 4; ++j) lt[i][j] = 0.0f;
#pragma unroll 16
            for (int kk = 0; kk < DHEAD; ++kk) {
                float4 a = *(float4*)&Qs[kk * LDP + ty * 4];
                float4 bb = *(float4*)&Ks[kk * LDP + tx * 4];
                float av[4] = {a.x, a.y, a.z, a.w};
                float bv[4] = {bb.x, bb.y, bb.z, bb.w};
#pragma unroll
                for (int i = 0; i < 4; ++i)
#pragma unroll
                    for (int j = 0; j < 4; ++j)
                        lt[i][j] = fmaf(av[i], bv[j], lt[i][j]);
            }
#pragma unroll
            for (int i = 0; i < 4; ++i)
#pragma unroll
                for (int j = 0; j < 4; ++j)
                    e[i][j] = __expf(lt[i][j] * 0.125f);
        }
#pragma unroll
        for (int i = 0; i < 4; ++i) {
            float4 ev = make_float4(e[i][0], e[i][1], e[i][2], e[i][3]);
            *(float4*)&Es[(ty * 4 + i) * LDP + tx * 4] = ev;
            psum[i] += (e[i][0] + e[i][1]) + (e[i][2] + e[i][3]);
            if (gattn) {
                size_t row = (size_t)((b * NHEAD + h) * SEQ + q0 + ty * 4 + i);
                *(float4*)&gattn[row * SEQ + kc + tx * 4] = ev;
            }
        }
        __syncthreads();

#pragma unroll 16
        for (int kk = 0; kk < 64; ++kk) {
            float4 vv = *(float4*)&Vs[kk * LDP + tx * 4];
#pragma unroll
            for (int i = 0; i < 4; ++i) {
                float p = Es[(ty * 4 + i) * LDP + kk];
                acc[i][0] = fmaf(p, vv.x, acc[i][0]);
                acc[i][1] = fmaf(p, vv.y, acc[i][1]);
                acc[i][2] = fmaf(p, vv.z, acc[i][2]);
                acc[i][3] = fmaf(p, vv.w, acc[i][3]);
            }
        }
    }

#pragma unroll
    for (int i = 0; i < 4; ++i) {
        psum[i] += __shfl_xor_sync(0xffffffffu, psum[i], 8);
        psum[i] += __shfl_xor_sync(0xffffffffu, psum[i], 4);
        psum[i] += __shfl_xor_sync(0xffffffffu, psum[i], 2);
        psum[i] += __shfl_xor_sync(0xffffffffu, psum[i], 1);
    }
    if (tx == 0) {
#pragma unroll
        for (int i = 0; i < 4; ++i)
            g_rowsum[(size_t)(b * NHEAD + h) * SEQ + q0 + ty * 4 + i] = psum[i];
    }

#pragma unroll
    for (int i = 0; i < 4; ++i) {
        float inv = 1.0f / psum[i];
        float4 o = make_float4(acc[i][0] * inv, acc[i][1] * inv,
                               acc[i][2] * inv, acc[i][3] * inv);
        *(float4*)&g_ctx[(size_t)(b * SEQ + q0 + ty * 4 + i) * DMODEL + h * DHEAD + tx * 4] = o;
    }
}

// -------------------- attn rescale: p = e / rowsum ------------------------
__global__ __launch_bounds__(256)
void attn_scale(float* __restrict__ attn) {
    size_t i = (size_t)blockIdx.x * 256 + threadIdx.x;   // float4 index
    size_t row = i >> 9;                                 // 512 float4 per row
    float inv = 1.0f / g_rowsum[row];
    float4* p = (float4*)attn;
    float4 v = p[i];
    v.x *= inv; v.y *= inv; v.z *= inv; v.w *= inv;
    p[i] = v;
}

// -------------------- LayerNorm ------------------------------------------
__global__ __launch_bounds__(256)
void ln_kernel(const float* __restrict__ gamma, const float* __restrict__ beta,
               float* __restrict__ out) {
    const int row = blockIdx.x;
    const int tid = threadIdx.x;
    __shared__ float red[8];

    float4 x = *(const float4*)&g_o[(size_t)row * DMODEL + tid * 4];
    float s = (x.x + x.y) + (x.z + x.w);
#pragma unroll
    for (int off = 16; off; off >>= 1) s += __shfl_xor_sync(0xffffffffu, s, off);
    if ((tid & 31) == 0) red[tid >> 5] = s;
    __syncthreads();
    float tot = 0.f;
#pragma unroll
    for (int i = 0; i < 8; ++i) tot += red[i];
    float mean = tot * (1.0f / 1024.0f);
    __syncthreads();

    float4 dx = make_float4(x.x - mean, x.y - mean, x.z - mean, x.w - mean);
    float ss = dx.x * dx.x + dx.y * dx.y + dx.z * dx.z + dx.w * dx.w;
#pragma unroll
    for (int off = 16; off; off >>= 1) ss += __shfl_xor_sync(0xffffffffu, ss, off);
    if ((tid & 31) == 0) red[tid >> 5] = ss;
    __syncthreads();
    float tss = 0.f;
#pragma unroll
    for (int i = 0; i < 8; ++i) tss += red[i];
    float var = tss * (1.0f / 1024.0f);
    float rstd = rsqrtf(var + 1e-3f);

    float4 g = *(const float4*)&gamma[tid * 4];
    float4 be = *(const float4*)&beta[tid * 4];
    float4 o;
    o.x = dx.x * rstd * g.x + be.x;
    o.y = dx.y * rstd * g.y + be.y;
    o.z = dx.z * rstd * g.z + be.z;
    o.w = dx.w * rstd * g.w + be.w;
    *(float4*)&out[(size_t)row * DMODEL + tid * 4] = o;
}

// -------------------- launcher --------------------------------------------
extern "C" void kernel_launch(void* const* d_in, const int* in_sizes, int n_in,
                              void* d_out, int out_size) {
    const float* query = (const float*)d_in[0];
    const float* key   = (const float*)d_in[1];
    const float* value = (const float*)d_in[2];
    const float* Wq = (const float*)d_in[3];
    const float* bq = (const float*)d_in[4];
    const float* Wk = (const float*)d_in[5];
    const float* bk = (const float*)d_in[6];
    const float* Wv = (const float*)d_in[7];
    const float* bv = (const float*)d_in[8];
    const float* Wo = (const float*)d_in[9];
    const float* bo = (const float*)d_in[10];
    const float* gamma = (const float*)d_in[11];
    const float* beta  = (const float*)d_in[12];

    float* out = (float*)d_out;
    float* attn = (out_size >= OUT_ELEMS + ATTN_ELEMS) ? (out + OUT_ELEMS) : nullptr;

    cudaFuncSetAttribute(attn_kernel, cudaFuncAttributeMaxDynamicSharedMemorySize,
                         ATTN_SMEM_BYTES);

    dim3 gproj(DMODEL / 128, NROWS / 128);   // (8, 32)
    gemm_tc<<<gproj, 256>>>(query, -1, Wq, bq, 0);
    gemm_tc<<<gproj, 256>>>(key,   -1, Wk, bk, 1);
    gemm_tc<<<gproj, 256>>>(value, -1, Wv, bv, 2);

    attn_kernel<<<dim3(SEQ / 64, NHEAD, BATCH), 256, ATTN_SMEM_BYTES>>>(attn);

    if (attn) {
        attn_scale<<<ATTN_ELEMS / 4 / 256, 256>>>(attn);
    }

    gemm_tc<<<gproj, 256>>>(nullptr, 3, Wo, bo, 4);   // g_ctx @ Wo -> g_o
    ln_kernel<<<NROWS, 256>>>(gamma, beta, out);
}

// round 4
// speedup vs baseline: 2.1162x; 1.6430x over previous
#include <cuda_runtime.h>
#include <cuda_bf16.h>
#include <math.h>
#include <stdint.h>

// Problem constants
#define SEQ   2048
#define BATCH 2
#define DMODEL 1024
#define NHEAD 16
#define DHEAD 64
#define NROWS (BATCH * SEQ)          // 4096
#define OUT_ELEMS   (NROWS * DMODEL)             // 4,194,304
#define ATTN_ELEMS  (BATCH * NHEAD * SEQ * SEQ)  // 134,217,728

// -------------------- device scratch (no allocations allowed) ------------
__device__ float g_ctx[NROWS * DMODEL];
__device__ float g_o[NROWS * DMODEL];
__device__ float g_rowsum[BATCH * NHEAD * SEQ];
// split-bf16 Q/K/V (hi + lo residual), layout [b, s, h*64+d]
__device__ __nv_bfloat16 g_qh[NROWS * DMODEL];
__device__ __nv_bfloat16 g_ql[NROWS * DMODEL];
__device__ __nv_bfloat16 g_kh[NROWS * DMODEL];
__device__ __nv_bfloat16 g_kl[NROWS * DMODEL];
__device__ __nv_bfloat16 g_vh[NROWS * DMODEL];
__device__ __nv_bfloat16 g_vl[NROWS * DMODEL];

// ==================== mma helpers ========================================
__device__ __forceinline__ void ldsm_x4(uint32_t (&r)[4], uint32_t addr) {
    asm volatile("ldmatrix.sync.aligned.m8n8.x4.shared.b16 {%0,%1,%2,%3}, [%4];"
                 : "=r"(r[0]), "=r"(r[1]), "=r"(r[2]), "=r"(r[3]) : "r"(addr));
}
__device__ __forceinline__ void ldsm_x4_t(uint32_t (&r)[4], uint32_t addr) {
    asm volatile("ldmatrix.sync.aligned.m8n8.x4.trans.shared.b16 {%0,%1,%2,%3}, [%4];"
                 : "=r"(r[0]), "=r"(r[1]), "=r"(r[2]), "=r"(r[3]) : "r"(addr));
}
__device__ __forceinline__ void mma16816(float (&c)[4], const uint32_t (&a)[4],
                                         uint32_t b0, uint32_t b1) {
    asm volatile(
        "mma.sync.aligned.m16n8k16.row.col.f32.bf16.bf16.f32 "
        "{%0,%1,%2,%3}, {%4,%5,%6,%7}, {%8,%9}, {%0,%1,%2,%3};"
        : "+f"(c[0]), "+f"(c[1]), "+f"(c[2]), "+f"(c[3])
        : "r"(a[0]), "r"(a[1]), "r"(a[2]), "r"(a[3]), "r"(b0), "r"(b1));
}
__device__ __forceinline__ uint32_t pack_hi(float x, float y) {
    __nv_bfloat162 h = __floats2bfloat162_rn(x, y);
    return *(uint32_t*)&h;
}

// ==================== tensor-core projection GEMM =========================
// C[4096,1024] = A(fp32) @ W(fp32) + bias via split-bf16 (3 MMAs).
// If bf_sel >= 0, write bf16 hi/lo outputs instead of fp32.
#define A_LD 40
#define B_LD 136

__global__ __launch_bounds__(256)
void gemm_tc(const float* __restrict__ A_ext, int a_sel,
             const float* __restrict__ W, const float* __restrict__ bias,
             int c_sel, int bf_sel) {
    __shared__ __nv_bfloat16 Ah[128][A_LD];
    __shared__ __nv_bfloat16 Al[128][A_LD];
    __shared__ __nv_bfloat16 Bh[32][B_LD];
    __shared__ __nv_bfloat16 Bl[32][B_LD];

    const float* A = A_ext ? A_ext : (a_sel == 3 ? g_ctx : g_o);
    float* C = (c_sel == 3) ? g_ctx : g_o;
    __nv_bfloat16 *OH = nullptr, *OL = nullptr;
    if (bf_sel == 0) { OH = g_qh; OL = g_ql; }
    else if (bf_sel == 1) { OH = g_kh; OL = g_kl; }
    else if (bf_sel == 2) { OH = g_vh; OL = g_vl; }

    const int tid = threadIdx.x;
    const int lane = tid & 31;
    const int warp = tid >> 5;
    const int wm = (warp & 3) * 32;
    const int wn = (warp >> 2) * 64;
    const int bm = blockIdx.y * 128;
    const int bn = blockIdx.x * 128;

    const int a_row = tid >> 1;
    const int a_col0 = (tid & 1) * 16;
    const int b_row = tid >> 3;
    const int b_col0 = (tid & 7) * 16;

    float acc[2][8][4];
#pragma unroll
    for (int i = 0; i < 2; ++i)
#pragma unroll
        for (int j = 0; j < 8; ++j)
#pragma unroll
            for (int r = 0; r < 4; ++r) acc[i][j][r] = 0.f;

    const int lr = lane & 15;
    const int lh = lane >> 4;

    for (int k0 = 0; k0 < DMODEL; k0 += 32) {
#pragma unroll
        for (int i = 0; i < 4; ++i) {
            const float* src = A + (size_t)(bm + a_row) * DMODEL + k0 + a_col0 + i * 4;
            float4 v = *(const float4*)src;
            float hx = __bfloat162float(__float2bfloat16_rn(v.x));
            float hy = __bfloat162float(__float2bfloat16_rn(v.y));
            float hz = __bfloat162float(__float2bfloat16_rn(v.z));
            float hw = __bfloat162float(__float2bfloat16_rn(v.w));
            int c = a_col0 + i * 4;
            *(uint32_t*)&Ah[a_row][c]     = pack_hi(v.x, v.y);
            *(uint32_t*)&Ah[a_row][c + 2] = pack_hi(v.z, v.w);
            *(uint32_t*)&Al[a_row][c]     = pack_hi(v.x - hx, v.y - hy);
            *(uint32_t*)&Al[a_row][c + 2] = pack_hi(v.z - hz, v.w - hw);
        }
#pragma unroll
        for (int i = 0; i < 4; ++i) {
            const float* src = W + (size_t)(k0 + b_row) * DMODEL + bn + b_col0 + i * 4;
            float4 v = *(const float4*)src;
            float hx = __bfloat162float(__float2bfloat16_rn(v.x));
            float hy = __bfloat162float(__float2bfloat16_rn(v.y));
            float hz = __bfloat162float(__float2bfloat16_rn(v.z));
            float hw = __bfloat162float(__float2bfloat16_rn(v.w));
            int c = b_col0 + i * 4;
            *(uint32_t*)&Bh[b_row][c]     = pack_hi(v.x, v.y);
            *(uint32_t*)&Bh[b_row][c + 2] = pack_hi(v.z, v.w);
            *(uint32_t*)&Bl[b_row][c]     = pack_hi(v.x - hx, v.y - hy);
            *(uint32_t*)&Bl[b_row][c + 2] = pack_hi(v.z - hz, v.w - hw);
        }
        __syncthreads();

#pragma unroll
        for (int ks = 0; ks < 2; ++ks) {
            uint32_t afh[2][4], afl[2][4];
#pragma unroll
            for (int mt = 0; mt < 2; ++mt) {
                ldsm_x4(afh[mt], (uint32_t)__cvta_generic_to_shared(
                    &Ah[wm + mt * 16 + lr][ks * 16 + lh * 8]));
                ldsm_x4(afl[mt], (uint32_t)__cvta_generic_to_shared(
                    &Al[wm + mt * 16 + lr][ks * 16 + lh * 8]));
            }
#pragma unroll
            for (int np = 0; np < 4; ++np) {
                uint32_t bfh[4], bfl[4];
                ldsm_x4_t(bfh, (uint32_t)__cvta_generic_to_shared(
                    &Bh[ks * 16 + lr][wn + np * 16 + lh * 8]));
                ldsm_x4_t(bfl, (uint32_t)__cvta_generic_to_shared(
                    &Bl[ks * 16 + lr][wn + np * 16 + lh * 8]));
#pragma unroll
                for (int mt = 0; mt < 2; ++mt) {
                    mma16816(acc[mt][2 * np],     afh[mt], bfh[0], bfh[1]);
                    mma16816(acc[mt][2 * np],     afh[mt], bfl[0], bfl[1]);
                    mma16816(acc[mt][2 * np],     afl[mt], bfh[0], bfh[1]);
                    mma16816(acc[mt][2 * np + 1], afh[mt], bfh[2], bfh[3]);
                    mma16816(acc[mt][2 * np + 1], afh[mt], bfl[2], bfl[3]);
                    mma16816(acc[mt][2 * np + 1], afl[mt], bfh[2], bfh[3]);
                }
            }
        }
        __syncthreads();
    }

    const int gid = lane >> 2;
    const int qid = lane & 3;
#pragma unroll
    for (int mt = 0; mt < 2; ++mt) {
#pragma unroll
        for (int nt = 0; nt < 8; ++nt) {
            int col = bn + wn + nt * 8 + qid * 2;
            float b0 = bias[col], b1 = bias[col + 1];
            int r0 = bm + wm + mt * 16 + gid;
            float v00 = acc[mt][nt][0] + b0, v01 = acc[mt][nt][1] + b1;
            float v10 = acc[mt][nt][2] + b0, v11 = acc[mt][nt][3] + b1;
            if (OH) {
                size_t p0 = (size_t)r0 * DMODEL + col;
                size_t p1 = (size_t)(r0 + 8) * DMODEL + col;
                __nv_bfloat16 h00 = __float2bfloat16_rn(v00);
                __nv_bfloat16 h01 = __float2bfloat16_rn(v01);
                __nv_bfloat16 h10 = __float2bfloat16_rn(v10);
                __nv_bfloat16 h11 = __float2bfloat16_rn(v11);
                *(uint32_t*)&OH[p0] = pack_hi(v00, v01);
                *(uint32_t*)&OL[p0] = pack_hi(v00 - __bfloat162float(h00),
                                              v01 - __bfloat162float(h01));
                *(uint32_t*)&OH[p1] = pack_hi(v10, v11);
                *(uint32_t*)&OL[p1] = pack_hi(v10 - __bfloat162float(h10),
                                              v11 - __bfloat162float(h11));
            } else {
                *(float2*)&C[(size_t)r0 * DMODEL + col] = make_float2(v00, v01);
                *(float2*)&C[(size_t)(r0 + 8) * DMODEL + col] = make_float2(v10, v11);
            }
        }
    }
}

// ==================== tensor-core attention ===============================
// Block: 64 q-rows x one (b,h). 8 warps: wy=warp&3 (16-row strip),
// wx=warp>>2 (32-col half). Split-bf16 3-MMA for S=QK^T and ctx=PV.
#define ALD 72
#define TCA_SMEM (6 * 64 * ALD * 2 + 128 * 4)

__global__ __launch_bounds__(256)
void attn_tc(float* __restrict__ gattn) {
    extern __shared__ __align__(16) char dsm[];
    __nv_bfloat16* Kh = (__nv_bfloat16*)dsm;          // also Q hi at start
    __nv_bfloat16* Kl = Kh + 64 * ALD;                // also Q lo at start
    __nv_bfloat16* Vh = Kl + 64 * ALD;
    __nv_bfloat16* Vl = Vh + 64 * ALD;
    __nv_bfloat16* Ph = Vl + 64 * ALD;
    __nv_bfloat16* Pl = Ph + 64 * ALD;
    float* sPart = (float*)(Pl + 64 * ALD);           // [2][64]

    const int tid = threadIdx.x;
    const int lane = tid & 31;
    const int warp = tid >> 5;
    const int wy = warp & 3;
    const int wx = warp >> 2;
    const int lr = lane & 15;
    const int lh = lane >> 4;
    const int gid = lane >> 2;
    const int qid = lane & 3;

    const int q0 = blockIdx.x * 64;
    const int h = blockIdx.y;
    const int b = blockIdx.z;

    const size_t head_off = (size_t)b * SEQ * DMODEL + h * DHEAD;

    // ---- load Q tile (64x64) hi/lo into Kh/Kl space, extract frags -------
    {
        const int row = tid >> 2;
        const int cg = (tid & 3) * 16;
        const size_t src = head_off + (size_t)(q0 + row) * DMODEL + cg;
        *(uint4*)&Kh[row * ALD + cg]     = *(const uint4*)&g_qh[src];
        *(uint4*)&Kh[row * ALD + cg + 8] = *(const uint4*)&g_qh[src + 8];
        *(uint4*)&Kl[row * ALD + cg]     = *(const uint4*)&g_ql[src];
        *(uint4*)&Kl[row * ALD + cg + 8] = *(const uint4*)&g_ql[src + 8];
    }
    __syncthreads();

    uint32_t aQh[4][4], aQl[4][4];
#pragma unroll
    for (int ks = 0; ks < 4; ++ks) {
        ldsm_x4(aQh[ks], (uint32_t)__cvta_generic_to_shared(
            &Kh[(wy * 16 + lr) * ALD + ks * 16 + lh * 8]));
        ldsm_x4(aQl[ks], (uint32_t)__cvta_generic_to_shared(
            &Kl[(wy * 16 + lr) * ALD + ks * 16 + lh * 8]));
    }

    float ctx[4][4];
#pragma unroll
    for (int j = 0; j < 4; ++j)
#pragma unroll
        for (int r = 0; r < 4; ++r) ctx[j][r] = 0.f;
    float psum0 = 0.f, psum1 = 0.f;

    const int row0 = wy * 16 + gid;       // local q row (first of pair)
    const size_t arow0 = (size_t)((b * NHEAD + h) * SEQ + q0 + row0);

    for (int kc = 0; kc < SEQ; kc += 64) {
        __syncthreads();   // protects Kh/Kl (Q frags done / prev chunk done)
        // ---- load K,V chunk hi/lo ----
        {
            const int row = tid >> 2;
            const int cg = (tid & 3) * 16;
            const size_t src = head_off + (size_t)(kc + row) * DMODEL + cg;
            *(uint4*)&Kh[row * ALD + cg]     = *(const uint4*)&g_kh[src];
            *(uint4*)&Kh[row * ALD + cg + 8] = *(const uint4*)&g_kh[src + 8];
            *(uint4*)&Kl[row * ALD + cg]     = *(const uint4*)&g_kl[src];
            *(uint4*)&Kl[row * ALD + cg + 8] = *(const uint4*)&g_kl[src + 8];
            *(uint4*)&Vh[row * ALD + cg]     = *(const uint4*)&g_vh[src];
            *(uint4*)&Vh[row * ALD + cg + 8] = *(const uint4*)&g_vh[src + 8];
            *(uint4*)&Vl[row * ALD + cg]     = *(const uint4*)&g_vl[src];
            *(uint4*)&Vl[row * ALD + cg + 8] = *(const uint4*)&g_vl[src + 8];
        }
        __syncthreads();

        // ---- S = Q K^T (64x64 tile; this warp: rows wy*16.., cols wx*32..)
        float s[4][4];
#pragma unroll
        for (int j = 0; j < 4; ++j)
#pragma unroll
            for (int r = 0; r < 4; ++r) s[j][r] = 0.f;

#pragma unroll
        for (int ks = 0; ks < 4; ++ks) {
            // K is [key][d] = col-major (k=d, n=key): non-trans ldsm, custom map
            uint32_t bKh[2][4], bKl[2][4];
            const int mat = lane >> 3, rr = lane & 7;
            const int keyo = (mat >> 1) * 8 + rr;
            const int dof = (mat & 1) * 8 + ks * 16;
#pragma unroll
            for (int g = 0; g < 2; ++g) {
                int key = wx * 32 + g * 16 + keyo;
                ldsm_x4(bKh[g], (uint32_t)__cvta_generic_to_shared(
                    &Kh[key * ALD + dof]));
                ldsm_x4(bKl[g], (uint32_t)__cvta_generic_to_shared(
                    &Kl[key * ALD + dof]));
            }
#pragma unroll
            for (int j = 0; j < 4; ++j) {
                const int g = j >> 1, p = (j & 1) * 2;
                mma16816(s[j], aQh[ks], bKh[g][p], bKh[g][p + 1]);
                mma16816(s[j], aQh[ks], bKl[g][p], bKl[g][p + 1]);
                mma16816(s[j], aQl[ks], bKh[g][p], bKh[g][p + 1]);
            }
        }

        // ---- exp, rowsum, store attn + P(hi/lo) ----
#pragma unroll
        for (int j = 0; j < 4; ++j) {
            float e0 = __expf(s[j][0] * 0.125f);
            float e1 = __expf(s[j][1] * 0.125f);
            float e2 = __expf(s[j][2] * 0.125f);
            float e3 = __expf(s[j][3] * 0.125f);
            psum0 += e0 + e1;
            psum1 += e2 + e3;
            const int col = wx * 32 + j * 8 + qid * 2;
            if (gattn) {
                __stcs((float2*)&gattn[arow0 * SEQ + kc + col], make_float2(e0, e1));
                __stcs((float2*)&gattn[(arow0 + 8) * SEQ + kc + col], make_float2(e2, e3));
            }
            __nv_bfloat16 h0 = __float2bfloat16_rn(e0);
            __nv_bfloat16 h1 = __float2bfloat16_rn(e1);
            __nv_bfloat16 h2 = __float2bfloat16_rn(e2);
            __nv_bfloat16 h3 = __float2bfloat16_rn(e3);
            *(uint32_t*)&Ph[row0 * ALD + col] = pack_hi(e0, e1);
            *(uint32_t*)&Ph[(row0 + 8) * ALD + col] = pack_hi(e2, e3);
            *(uint32_t*)&Pl[row0 * ALD + col] =
                pack_hi(e0 - __bfloat162float(h0), e1 - __bfloat162float(h1));
            *(uint32_t*)&Pl[(row0 + 8) * ALD + col] =
                pack_hi(e2 - __bfloat162float(h2), e3 - __bfloat162float(h3));
        }
        __syncthreads();

        // ---- ctx += P V  (this warp: rows wy*16.., d-cols wx*32..) -------
#pragma unroll
        for (int ks = 0; ks < 4; ++ks) {
            uint32_t aPh[4], aPl[4];
            ldsm_x4(aPh, (uint32_t)__cvta_generic_to_shared(
                &Ph[(wy * 16 + lr) * ALD + ks * 16 + lh * 8]));
            ldsm_x4(aPl, (uint32_t)__cvta_generic_to_shared(
                &Pl[(wy * 16 + lr) * ALD + ks * 16 + lh * 8]));
#pragma unroll
            for (int np = 0; np < 2; ++np) {
                uint32_t bVh[4], bVl[4];
                ldsm_x4_t(bVh, (uint32_t)__cvta_generic_to_shared(
                    &Vh[(ks * 16 + lr) * ALD + wx * 32 + np * 16 + lh * 8]));
                ldsm_x4_t(bVl, (uint32_t)__cvta_generic_to_shared(
                    &Vl[(ks * 16 + lr) * ALD + wx * 32 + np * 16 + lh * 8]));
                mma16816(ctx[2 * np],     aPh, bVh[0], bVh[1]);
                mma16816(ctx[2 * np],     aPh, bVl[0], bVl[1]);
                mma16816(ctx[2 * np],     aPl, bVh[0], bVh[1]);
                mma16816(ctx[2 * np + 1], aPh, bVh[2], bVh[3]);
                mma16816(ctx[2 * np + 1], aPh, bVl[2], bVl[3]);
                mma16816(ctx[2 * np + 1], aPl, bVh[2], bVh[3]);
            }
        }
    }

    // ---- rowsum reduce + normalize + store ctx ---------------------------
    psum0 += __shfl_xor_sync(0xffffffffu, psum0, 1);
    psum0 += __shfl_xor_sync(0xffffffffu, psum0, 2);
    psum1 += __shfl_xor_sync(0xffffffffu, psum1, 1);
    psum1 += __shfl_xor_sync(0xffffffffu, psum1, 2);
    if (qid == 0) {
        sPart[wx * 64 + row0] = psum0;
        sPart[wx * 64 + row0 + 8] = psum1;
    }
    __syncthreads();
    float tot0 = sPart[row0] + sPart[64 + row0];
    float tot1 = sPart[row0 + 8] + sPart[64 + row0 + 8];
    if (wx == 0 && qid == 0) {
        g_rowsum[arow0] = tot0;
        g_rowsum[arow0 + 8] = tot1;
    }
    float inv0 = 1.0f / tot0, inv1 = 1.0f / tot1;
#pragma unroll
    for (int j = 0; j < 4; ++j) {
        const int col = wx * 32 + j * 8 + qid * 2;
        size_t p0 = (size_t)(b * SEQ + q0 + row0) * DMODEL + h * DHEAD + col;
        size_t p1 = (size_t)(b * SEQ + q0 + row0 + 8) * DMODEL + h * DHEAD + col;
        *(float2*)&g_ctx[p0] = make_float2(ctx[j][0] * inv0, ctx[j][1] * inv0);
        *(float2*)&g_ctx[p1] = make_float2(ctx[j][2] * inv1, ctx[j][3] * inv1);
    }
}

// -------------------- attn rescale: p = e / rowsum ------------------------
__global__ __launch_bounds__(256)
void attn_scale(float* __restrict__ attn) {
    size_t i = (size_t)blockIdx.x * 256 + threadIdx.x;
    size_t row = i >> 9;
    float inv = 1.0f / g_rowsum[row];
    float4* p = (float4*)attn;
    float4 v = p[i];
    v.x *= inv; v.y *= inv; v.z *= inv; v.w *= inv;
    p[i] = v;
}

// -------------------- LayerNorm ------------------------------------------
__global__ __launch_bounds__(256)
void ln_kernel(const float* __restrict__ gamma, const float* __restrict__ beta,
               float* __restrict__ out) {
    const int row = blockIdx.x;
    const int tid = threadIdx.x;
    __shared__ float red[8];

    float4 x = *(const float4*)&g_o[(size_t)row * DMODEL + tid * 4];
    float s = (x.x + x.y) + (x.z + x.w);
#pragma unroll
    for (int off = 16; off; off >>= 1) s += __shfl_xor_sync(0xffffffffu, s, off);
    if ((tid & 31) == 0) red[tid >> 5] = s;
    __syncthreads();
    float tot = 0.f;
#pragma unroll
    for (int i = 0; i < 8; ++i) tot += red[i];
    float mean = tot * (1.0f / 1024.0f);
    __syncthreads();

    float4 dx = make_float4(x.x - mean, x.y - mean, x.z - mean, x.w - mean);
    float ss = dx.x * dx.x + dx.y * dx.y + dx.z * dx.z + dx.w * dx.w;
#pragma unroll
    for (int off = 16; off; off >>= 1) ss += __shfl_xor_sync(0xffffffffu, ss, off);
    if ((tid & 31) == 0) red[tid >> 5] = ss;
    __syncthreads();
    float tss = 0.f;
#pragma unroll
    for (int i = 0; i < 8; ++i) tss += red[i];
    float var = tss * (1.0f / 1024.0f);
    float rstd = rsqrtf(var + 1e-3f);

    float4 g = *(const float4*)&gamma[tid * 4];
    float4 be = *(const float4*)&beta[tid * 4];
    float4 o;
    o.x = dx.x * rstd * g.x + be.x;
    o.y = dx.y * rstd * g.y + be.y;
    o.z = dx.z * rstd * g.z + be.z;
    o.w = dx.w * rstd * g.w + be.w;
    *(float4*)&out[(size_t)row * DMODEL + tid * 4] = o;
}

// -------------------- launcher --------------------------------------------
extern "C" void kernel_launch(void* const* d_in, const int* in_sizes, int n_in,
                              void* d_out, int out_size) {
    const float* query = (const float*)d_in[0];
    const float* key   = (const float*)d_in[1];
    const float* value = (const float*)d_in[2];
    const float* Wq = (const float*)d_in[3];
    const float* bq = (const float*)d_in[4];
    const float* Wk = (const float*)d_in[5];
    const float* bk = (const float*)d_in[6];
    const float* Wv = (const float*)d_in[7];
    const float* bv = (const float*)d_in[8];
    const float* Wo = (const float*)d_in[9];
    const float* bo = (const float*)d_in[10];
    const float* gamma = (const float*)d_in[11];
    const float* beta  = (const float*)d_in[12];

    float* out = (float*)d_out;
    float* attn = (out_size >= OUT_ELEMS + ATTN_ELEMS) ? (out + OUT_ELEMS) : nullptr;

    cudaFuncSetAttribute(attn_tc, cudaFuncAttributeMaxDynamicSharedMemorySize,
                         TCA_SMEM);

    dim3 gproj(DMODEL / 128, NROWS / 128);
    gemm_tc<<<gproj, 256>>>(query, -1, Wq, bq, -1, 0);
    gemm_tc<<<gproj, 256>>>(key,   -1, Wk, bk, -1, 1);
    gemm_tc<<<gproj, 256>>>(value, -1, Wv, bv, -1, 2);

    attn_tc<<<dim3(SEQ / 64, NHEAD, BATCH), 256, TCA_SMEM>>>(attn);

    if (attn) {
        attn_scale<<<ATTN_ELEMS / 4 / 256, 256>>>(attn);
    }

    gemm_tc<<<gproj, 256>>>(nullptr, 3, Wo, bo, -1, -1);  // g_ctx @ Wo -> g_o
    ln_kernel<<<NROWS, 256>>>(gamma, beta, out);
}

// round 5
// speedup vs baseline: 2.1780x; 1.0292x over previous
#include <cuda_runtime.h>
#include <cuda_bf16.h>
#include <math.h>
#include <stdint.h>

// Problem constants
#define SEQ   2048
#define BATCH 2
#define DMODEL 1024
#define NHEAD 16
#define DHEAD 64
#define NROWS (BATCH * SEQ)          // 4096
#define OUT_ELEMS   (NROWS * DMODEL)             // 4,194,304
#define ATTN_ELEMS  (BATCH * NHEAD * SEQ * SEQ)  // 134,217,728

// -------------------- device scratch (no allocations allowed) ------------
__device__ float g_ctx[NROWS * DMODEL];
__device__ float g_o[NROWS * DMODEL];
__device__ float g_rowsum[BATCH * NHEAD * SEQ];
// split-bf16 Q/K/V (hi + lo residual), layout [b, s, h*64+d]
__device__ __nv_bfloat16 g_qh[NROWS * DMODEL];
__device__ __nv_bfloat16 g_ql[NROWS * DMODEL];
__device__ __nv_bfloat16 g_kh[NROWS * DMODEL];
__device__ __nv_bfloat16 g_kl[NROWS * DMODEL];
__device__ __nv_bfloat16 g_vh[NROWS * DMODEL];
__device__ __nv_bfloat16 g_vl[NROWS * DMODEL];

// ==================== mma helpers ========================================
__device__ __forceinline__ void ldsm_x4(uint32_t (&r)[4], uint32_t addr) {
    asm volatile("ldmatrix.sync.aligned.m8n8.x4.shared.b16 {%0,%1,%2,%3}, [%4];"
                 : "=r"(r[0]), "=r"(r[1]), "=r"(r[2]), "=r"(r[3]) : "r"(addr));
}
__device__ __forceinline__ void ldsm_x4_t(uint32_t (&r)[4], uint32_t addr) {
    asm volatile("ldmatrix.sync.aligned.m8n8.x4.trans.shared.b16 {%0,%1,%2,%3}, [%4];"
                 : "=r"(r[0]), "=r"(r[1]), "=r"(r[2]), "=r"(r[3]) : "r"(addr));
}
__device__ __forceinline__ void mma16816(float (&c)[4], const uint32_t (&a)[4],
                                         uint32_t b0, uint32_t b1) {
    asm volatile(
        "mma.sync.aligned.m16n8k16.row.col.f32.bf16.bf16.f32 "
        "{%0,%1,%2,%3}, {%4,%5,%6,%7}, {%8,%9}, {%0,%1,%2,%3};"
        : "+f"(c[0]), "+f"(c[1]), "+f"(c[2]), "+f"(c[3])
        : "r"(a[0]), "r"(a[1]), "r"(a[2]), "r"(a[3]), "r"(b0), "r"(b1));
}
__device__ __forceinline__ uint32_t pack_hi(float x, float y) {
    __nv_bfloat162 h = __floats2bfloat162_rn(x, y);
    return *(uint32_t*)&h;
}

// ==================== tensor-core projection GEMM =========================
// mode 0: z in {0,1,2} selects (query,Wq)->qh/ql etc.  mode 1: g_ctx@Wo->g_o.
#define A_LD 40
#define B_LD 136

__global__ __launch_bounds__(256)
void gemm_fused(const float* __restrict__ A0, const float* __restrict__ A1,
                const float* __restrict__ A2,
                const float* __restrict__ W0, const float* __restrict__ W1,
                const float* __restrict__ W2,
                const float* __restrict__ b0p, const float* __restrict__ b1p,
                const float* __restrict__ b2p, int mode) {
    __shared__ __nv_bfloat16 Ah[128][A_LD];
    __shared__ __nv_bfloat16 Al[128][A_LD];
    __shared__ __nv_bfloat16 Bh[32][B_LD];
    __shared__ __nv_bfloat16 Bl[32][B_LD];

    const float *A, *W, *bias;
    __nv_bfloat16 *OH = nullptr, *OL = nullptr;
    float* C = g_o;
    if (mode == 0) {
        int z = blockIdx.z;
        A = (z == 0) ? A0 : (z == 1) ? A1 : A2;
        W = (z == 0) ? W0 : (z == 1) ? W1 : W2;
        bias = (z == 0) ? b0p : (z == 1) ? b1p : b2p;
        OH = (z == 0) ? g_qh : (z == 1) ? g_kh : g_vh;
        OL = (z == 0) ? g_ql : (z == 1) ? g_kl : g_vl;
    } else {
        A = g_ctx; W = W0; bias = b0p;
    }

    const int tid = threadIdx.x;
    const int lane = tid & 31;
    const int warp = tid >> 5;
    const int wm = (warp & 3) * 32;
    const int wn = (warp >> 2) * 64;
    const int bm = blockIdx.y * 128;
    const int bn = blockIdx.x * 128;

    const int a_row = tid >> 1;
    const int a_col0 = (tid & 1) * 16;
    const int b_row = tid >> 3;
    const int b_col0 = (tid & 7) * 16;

    float acc[2][8][4];
#pragma unroll
    for (int i = 0; i < 2; ++i)
#pragma unroll
        for (int j = 0; j < 8; ++j)
#pragma unroll
            for (int r = 0; r < 4; ++r) acc[i][j][r] = 0.f;

    const int lr = lane & 15;
    const int lh = lane >> 4;

    for (int k0 = 0; k0 < DMODEL; k0 += 32) {
#pragma unroll
        for (int i = 0; i < 4; ++i) {
            const float* src = A + (size_t)(bm + a_row) * DMODEL + k0 + a_col0 + i * 4;
            float4 v = *(const float4*)src;
            float hx = __bfloat162float(__float2bfloat16_rn(v.x));
            float hy = __bfloat162float(__float2bfloat16_rn(v.y));
            float hz = __bfloat162float(__float2bfloat16_rn(v.z));
            float hw = __bfloat162float(__float2bfloat16_rn(v.w));
            int c = a_col0 + i * 4;
            *(uint32_t*)&Ah[a_row][c]     = pack_hi(v.x, v.y);
            *(uint32_t*)&Ah[a_row][c + 2] = pack_hi(v.z, v.w);
            *(uint32_t*)&Al[a_row][c]     = pack_hi(v.x - hx, v.y - hy);
            *(uint32_t*)&Al[a_row][c + 2] = pack_hi(v.z - hz, v.w - hw);
        }
#pragma unroll
        for (int i = 0; i < 4; ++i) {
            const float* src = W + (size_t)(k0 + b_row) * DMODEL + bn + b_col0 + i * 4;
            float4 v = *(const float4*)src;
            float hx = __bfloat162float(__float2bfloat16_rn(v.x));
            float hy = __bfloat162float(__float2bfloat16_rn(v.y));
            float hz = __bfloat162float(__float2bfloat16_rn(v.z));
            float hw = __bfloat162float(__float2bfloat16_rn(v.w));
            int c = b_col0 + i * 4;
            *(uint32_t*)&Bh[b_row][c]     = pack_hi(v.x, v.y);
            *(uint32_t*)&Bh[b_row][c + 2] = pack_hi(v.z, v.w);
            *(uint32_t*)&Bl[b_row][c]     = pack_hi(v.x - hx, v.y - hy);
            *(uint32_t*)&Bl[b_row][c + 2] = pack_hi(v.z - hz, v.w - hw);
        }
        __syncthreads();

#pragma unroll
        for (int ks = 0; ks < 2; ++ks) {
            uint32_t afh[2][4], afl[2][4];
#pragma unroll
            for (int mt = 0; mt < 2; ++mt) {
                ldsm_x4(afh[mt], (uint32_t)__cvta_generic_to_shared(
                    &Ah[wm + mt * 16 + lr][ks * 16 + lh * 8]));
                ldsm_x4(afl[mt], (uint32_t)__cvta_generic_to_shared(
                    &Al[wm + mt * 16 + lr][ks * 16 + lh * 8]));
            }
#pragma unroll
            for (int np = 0; np < 4; ++np) {
                uint32_t bfh[4], bfl[4];
                ldsm_x4_t(bfh, (uint32_t)__cvta_generic_to_shared(
                    &Bh[ks * 16 + lr][wn + np * 16 + lh * 8]));
                ldsm_x4_t(bfl, (uint32_t)__cvta_generic_to_shared(
                    &Bl[ks * 16 + lr][wn + np * 16 + lh * 8]));
#pragma unroll
                for (int mt = 0; mt < 2; ++mt) {
                    mma16816(acc[mt][2 * np],     afh[mt], bfh[0], bfh[1]);
                    mma16816(acc[mt][2 * np],     afh[mt], bfl[0], bfl[1]);
                    mma16816(acc[mt][2 * np],     afl[mt], bfh[0], bfh[1]);
                    mma16816(acc[mt][2 * np + 1], afh[mt], bfh[2], bfh[3]);
                    mma16816(acc[mt][2 * np + 1], afh[mt], bfl[2], bfl[3]);
                    mma16816(acc[mt][2 * np + 1], afl[mt], bfh[2], bfh[3]);
                }
            }
        }
        __syncthreads();
    }

    const int gid = lane >> 2;
    const int qid = lane & 3;
#pragma unroll
    for (int mt = 0; mt < 2; ++mt) {
#pragma unroll
        for (int nt = 0; nt < 8; ++nt) {
            int col = bn + wn + nt * 8 + qid * 2;
            float bb0 = bias[col], bb1 = bias[col + 1];
            int r0 = bm + wm + mt * 16 + gid;
            float v00 = acc[mt][nt][0] + bb0, v01 = acc[mt][nt][1] + bb1;
            float v10 = acc[mt][nt][2] + bb0, v11 = acc[mt][nt][3] + bb1;
            if (OH) {
                size_t p0 = (size_t)r0 * DMODEL + col;
                size_t p1 = (size_t)(r0 + 8) * DMODEL + col;
                __nv_bfloat16 h00 = __float2bfloat16_rn(v00);
                __nv_bfloat16 h01 = __float2bfloat16_rn(v01);
                __nv_bfloat16 h10 = __float2bfloat16_rn(v10);
                __nv_bfloat16 h11 = __float2bfloat16_rn(v11);
                *(uint32_t*)&OH[p0] = pack_hi(v00, v01);
                *(uint32_t*)&OL[p0] = pack_hi(v00 - __bfloat162float(h00),
                                              v01 - __bfloat162float(h01));
                *(uint32_t*)&OH[p1] = pack_hi(v10, v11);
                *(uint32_t*)&OL[p1] = pack_hi(v10 - __bfloat162float(h10),
                                              v11 - __bfloat162float(h11));
            } else {
                *(float2*)&C[(size_t)r0 * DMODEL + col] = make_float2(v00, v01);
                *(float2*)&C[(size_t)(r0 + 8) * DMODEL + col] = make_float2(v10, v11);
            }
        }
    }
}

// ==================== tensor-core attention v2 ============================
// Block: 64 q-rows x one (b,h). 8 warps: wy=warp&3 (16-row strip),
// wx=warp>>2 (32-key half). P kept in registers (FA2 fragment trick).
// Each warp accumulates ctx over its key-half for full d=64; one final
// cross-wx reduction through smem.
#define ALD 72
#define TILE_B (64 * ALD * 2)                 // 9216 bytes per bf16 tile
#define TCA_SMEM (6 * TILE_B + 512 + 64)

__global__ __launch_bounds__(256, 2)
void attn_tc(float* __restrict__ gattn) {
    extern __shared__ __align__(16) char dsm[];
    __nv_bfloat16* Qh = (__nv_bfloat16*)dsm;
    __nv_bfloat16* Ql = (__nv_bfloat16*)(dsm + 1 * TILE_B);
    __nv_bfloat16* Kh = (__nv_bfloat16*)(dsm + 2 * TILE_B);
    __nv_bfloat16* Kl = (__nv_bfloat16*)(dsm + 3 * TILE_B);
    __nv_bfloat16* Vh = (__nv_bfloat16*)(dsm + 4 * TILE_B);
    __nv_bfloat16* Vl = (__nv_bfloat16*)(dsm + 5 * TILE_B);
    float* sPart = (float*)(dsm + 6 * TILE_B);      // [2][64]
    float* red = (float*)(dsm + 2 * TILE_B);        // aliases Kh/Kl: 64x68 fp32

    const int tid = threadIdx.x;
    const int lane = tid & 31;
    const int warp = tid >> 5;
    const int wy = warp & 3;
    const int wx = warp >> 2;
    const int lr = lane & 15;
    const int lh = lane >> 4;
    const int gid = lane >> 2;
    const int qid = lane & 3;

    const int q0 = blockIdx.x * 64;
    const int h = blockIdx.y;
    const int b = blockIdx.z;
    const size_t head_off = (size_t)b * SEQ * DMODEL + h * DHEAD;

    // ---- load Q tile (64x64) hi/lo into dedicated smem -------------------
    {
        const int row = tid >> 2;
        const int cg = (tid & 3) * 16;
        const size_t src = head_off + (size_t)(q0 + row) * DMODEL + cg;
        *(uint4*)&Qh[row * ALD + cg]     = *(const uint4*)&g_qh[src];
        *(uint4*)&Qh[row * ALD + cg + 8] = *(const uint4*)&g_qh[src + 8];
        *(uint4*)&Ql[row * ALD + cg]     = *(const uint4*)&g_ql[src];
        *(uint4*)&Ql[row * ALD + cg + 8] = *(const uint4*)&g_ql[src + 8];
    }

    float ctx[8][4];
#pragma unroll
    for (int j = 0; j < 8; ++j)
#pragma unroll
        for (int r = 0; r < 4; ++r) ctx[j][r] = 0.f;
    float psum0 = 0.f, psum1 = 0.f;

    const int row0 = wy * 16 + gid;
    const size_t arow0 = (size_t)((b * NHEAD + h) * SEQ + q0 + row0);

    for (int kc = 0; kc < SEQ; kc += 64) {
        __syncthreads();   // prev chunk's PV reads done; Q store (1st iter)
        {
            const int row = tid >> 2;
            const int cg = (tid & 3) * 16;
            const size_t src = head_off + (size_t)(kc + row) * DMODEL + cg;
            *(uint4*)&Kh[row * ALD + cg]     = *(const uint4*)&g_kh[src];
            *(uint4*)&Kh[row * ALD + cg + 8] = *(const uint4*)&g_kh[src + 8];
            *(uint4*)&Kl[row * ALD + cg]     = *(const uint4*)&g_kl[src];
            *(uint4*)&Kl[row * ALD + cg + 8] = *(const uint4*)&g_kl[src + 8];
            *(uint4*)&Vh[row * ALD + cg]     = *(const uint4*)&g_vh[src];
            *(uint4*)&Vh[row * ALD + cg + 8] = *(const uint4*)&g_vh[src + 8];
            *(uint4*)&Vl[row * ALD + cg]     = *(const uint4*)&g_vl[src];
            *(uint4*)&Vl[row * ALD + cg + 8] = *(const uint4*)&g_vl[src + 8];
        }
        __syncthreads();

        // ---- S = Q K^T (rows wy*16.., keys wx*32..) ----------------------
        float s[4][4];
#pragma unroll
        for (int j = 0; j < 4; ++j)
#pragma unroll
            for (int r = 0; r < 4; ++r) s[j][r] = 0.f;

#pragma unroll
        for (int ks = 0; ks < 4; ++ks) {
            uint32_t aQh[4], aQl[4];
            ldsm_x4(aQh, (uint32_t)__cvta_generic_to_shared(
                &Qh[(wy * 16 + lr) * ALD + ks * 16 + lh * 8]));
            ldsm_x4(aQl, (uint32_t)__cvta_generic_to_shared(
                &Ql[(wy * 16 + lr) * ALD + ks * 16 + lh * 8]));
            // K is [key][d]: non-trans ldsm with custom per-lane map
            uint32_t bKh[2][4], bKl[2][4];
            const int mat = lane >> 3, rr = lane & 7;
            const int keyo = (mat >> 1) * 8 + rr;
            const int dof = (mat & 1) * 8 + ks * 16;
#pragma unroll
            for (int g = 0; g < 2; ++g) {
                int key = wx * 32 + g * 16 + keyo;
                ldsm_x4(bKh[g], (uint32_t)__cvta_generic_to_shared(
                    &Kh[key * ALD + dof]));
                ldsm_x4(bKl[g], (uint32_t)__cvta_generic_to_shared(
                    &Kl[key * ALD + dof]));
            }
#pragma unroll
            for (int j = 0; j < 4; ++j) {
                const int g = j >> 1, p = (j & 1) * 2;
                mma16816(s[j], aQh, bKh[g][p], bKh[g][p + 1]);
                mma16816(s[j], aQh, bKl[g][p], bKl[g][p + 1]);
                mma16816(s[j], aQl, bKh[g][p], bKh[g][p + 1]);
            }
        }

        // ---- exp, rowsum, attn store; build P A-fragments in regs --------
        uint32_t aPh[2][4], aPl[2][4];
#pragma unroll
        for (int j = 0; j < 4; ++j) {
            float e0 = __expf(s[j][0] * 0.125f);
            float e1 = __expf(s[j][1] * 0.125f);
            float e2 = __expf(s[j][2] * 0.125f);
            float e3 = __expf(s[j][3] * 0.125f);
            psum0 += e0 + e1;
            psum1 += e2 + e3;
            const int col = wx * 32 + j * 8 + qid * 2;
            if (gattn) {
                __stcs((float2*)&gattn[arow0 * SEQ + kc + col], make_float2(e0, e1));
                __stcs((float2*)&gattn[(arow0 + 8) * SEQ + kc + col], make_float2(e2, e3));
            }
            float l0 = e0 - __bfloat162float(__float2bfloat16_rn(e0));
            float l1 = e1 - __bfloat162float(__float2bfloat16_rn(e1));
            float l2 = e2 - __bfloat162float(__float2bfloat16_rn(e2));
            float l3 = e3 - __bfloat162float(__float2bfloat16_rn(e3));
            const int t = j >> 1, half = j & 1;   // k16-slice, k-half
            aPh[t][half * 2 + 0] = pack_hi(e0, e1);
            aPh[t][half * 2 + 1] = pack_hi(e2, e3);
            aPl[t][half * 2 + 0] = pack_hi(l0, l1);
            aPl[t][half * 2 + 1] = pack_hi(l2, l3);
        }

        // ---- ctx += P V over this warp's 32-key slice, full d=64 ---------
#pragma unroll
        for (int t = 0; t < 2; ++t) {
            const int kb = wx * 32 + t * 16;
#pragma unroll
            for (int np = 0; np < 4; ++np) {
                uint32_t bVh[4], bVl[4];
                ldsm_x4_t(bVh, (uint32_t)__cvta_generic_to_shared(
                    &Vh[(kb + lr) * ALD + np * 16 + lh * 8]));
                ldsm_x4_t(bVl, (uint32_t)__cvta_generic_to_shared(
                    &Vl[(kb + lr) * ALD + np * 16 + lh * 8]));
                mma16816(ctx[2 * np],     aPh[t], bVh[0], bVh[1]);
                mma16816(ctx[2 * np],     aPh[t], bVl[0], bVl[1]);
                mma16816(ctx[2 * np],     aPl[t], bVh[0], bVh[1]);
                mma16816(ctx[2 * np + 1], aPh[t], bVh[2], bVh[3]);
                mma16816(ctx[2 * np + 1], aPh[t], bVl[2], bVl[3]);
                mma16816(ctx[2 * np + 1], aPl[t], bVh[2], bVh[3]);
            }
        }
    }

    // ---- rowsum partials + cross-wx ctx reduction ------------------------
    psum0 += __shfl_xor_sync(0xffffffffu, psum0, 1);
    psum0 += __shfl_xor_sync(0xffffffffu, psum0, 2);
    psum1 += __shfl_xor_sync(0xffffffffu, psum1, 1);
    psum1 += __shfl_xor_sync(0xffffffffu, psum1, 2);
    __syncthreads();    // all PV reads of K/V smem done; safe to alias 'red'
    if (qid == 0) {
        sPart[wx * 64 + row0] = psum0;
        sPart[wx * 64 + row0 + 8] = psum1;
    }
    if (wx == 1) {
#pragma unroll
        for (int j = 0; j < 8; ++j) {
            *(float2*)&red[row0 * 68 + j * 8 + qid * 2] =
                make_float2(ctx[j][0], ctx[j][1]);
            *(float2*)&red[(row0 + 8) * 68 + j * 8 + qid * 2] =
                make_float2(ctx[j][2], ctx[j][3]);
        }
    }
    __syncthreads();
    if (wx == 0) {
        float tot0 = sPart[row0] + sPart[64 + row0];
        float tot1 = sPart[row0 + 8] + sPart[64 + row0 + 8];
        if (qid == 0) {
            g_rowsum[arow0] = tot0;
            g_rowsum[arow0 + 8] = tot1;
        }
        float inv0 = 1.0f / tot0, inv1 = 1.0f / tot1;
#pragma unroll
        for (int j = 0; j < 8; ++j) {
            const int col = j * 8 + qid * 2;
            float2 o0 = *(float2*)&red[row0 * 68 + col];
            float2 o1 = *(float2*)&red[(row0 + 8) * 68 + col];
            o0.x = (ctx[j][0] + o0.x) * inv0;
            o0.y = (ctx[j][1] + o0.y) * inv0;
            o1.x = (ctx[j][2] + o1.x) * inv1;
            o1.y = (ctx[j][3] + o1.y) * inv1;
            size_t p0 = (size_t)(b * SEQ + q0 + row0) * DMODEL + h * DHEAD + col;
            size_t p1 = (size_t)(b * SEQ + q0 + row0 + 8) * DMODEL + h * DHEAD + col;
            *(float2*)&g_ctx[p0] = o0;
            *(float2*)&g_ctx[p1] = o1;
        }
    }
}

// -------------------- attn rescale: p = e / rowsum ------------------------
__global__ __launch_bounds__(256)
void attn_scale(float* __restrict__ attn) {
    size_t i = (size_t)blockIdx.x * 256 + threadIdx.x;
    size_t row = i >> 9;
    float inv = 1.0f / g_rowsum[row];
    float4* p = (float4*)attn;
    float4 v = p[i];
    v.x *= inv; v.y *= inv; v.z *= inv; v.w *= inv;
    p[i] = v;
}

// -------------------- LayerNorm ------------------------------------------
__global__ __launch_bounds__(256)
void ln_kernel(const float* __restrict__ gamma, const float* __restrict__ beta,
               float* __restrict__ out) {
    const int row = blockIdx.x;
    const int tid = threadIdx.x;
    __shared__ float red[8];

    float4 x = *(const float4*)&g_o[(size_t)row * DMODEL + tid * 4];
    float s = (x.x + x.y) + (x.z + x.w);
#pragma unroll
    for (int off = 16; off; off >>= 1) s += __shfl_xor_sync(0xffffffffu, s, off);
    if ((tid & 31) == 0) red[tid >> 5] = s;
    __syncthreads();
    float tot = 0.f;
#pragma unroll
    for (int i = 0; i < 8; ++i) tot += red[i];
    float mean = tot * (1.0f / 1024.0f);
    __syncthreads();

    float4 dx = make_float4(x.x - mean, x.y - mean, x.z - mean, x.w - mean);
    float ss = dx.x * dx.x + dx.y * dx.y + dx.z * dx.z + dx.w * dx.w;
#pragma unroll
    for (int off = 16; off; off >>= 1) ss += __shfl_xor_sync(0xffffffffu, ss, off);
    if ((tid & 31) == 0) red[tid >> 5] = ss;
    __syncthreads();
    float tss = 0.f;
#pragma unroll
    for (int i = 0; i < 8; ++i) tss += red[i];
    float var = tss * (1.0f / 1024.0f);
    float rstd = rsqrtf(var + 1e-3f);

    float4 g = *(const float4*)&gamma[tid * 4];
    float4 be = *(const float4*)&beta[tid * 4];
    float4 o;
    o.x = dx.x * rstd * g.x + be.x;
    o.y = dx.y * rstd * g.y + be.y;
    o.z = dx.z * rstd * g.z + be.z;
    o.w = dx.w * rstd * g.w + be.w;
    *(float4*)&out[(size_t)row * DMODEL + tid * 4] = o;
}

// -------------------- launcher --------------------------------------------
extern "C" void kernel_launch(void* const* d_in, const int* in_sizes, int n_in,
                              void* d_out, int out_size) {
    const float* query = (const float*)d_in[0];
    const float* key   = (const float*)d_in[1];
    const float* value = (const float*)d_in[2];
    const float* Wq = (const float*)d_in[3];
    const float* bq = (const float*)d_in[4];
    const float* Wk = (const float*)d_in[5];
    const float* bk = (const float*)d_in[6];
    const float* Wv = (const float*)d_in[7];
    const float* bv = (const float*)d_in[8];
    const float* Wo = (const float*)d_in[9];
    const float* bo = (const float*)d_in[10];
    const float* gamma = (const float*)d_in[11];
    const float* beta  = (const float*)d_in[12];

    float* out = (float*)d_out;
    float* attn = (out_size >= OUT_ELEMS + ATTN_ELEMS) ? (out + OUT_ELEMS) : nullptr;

    cudaFuncSetAttribute(attn_tc, cudaFuncAttributeMaxDynamicSharedMemorySize,
                         TCA_SMEM);

    dim3 gqkv(DMODEL / 128, NROWS / 128, 3);
    gemm_fused<<<gqkv, 256>>>(query, key, value, Wq, Wk, Wv, bq, bk, bv, 0);

    attn_tc<<<dim3(SEQ / 64, NHEAD, BATCH), 256, TCA_SMEM>>>(attn);

    if (attn) {
        attn_scale<<<ATTN_ELEMS / 4 / 256, 256>>>(attn);
    }

    dim3 gproj(DMODEL / 128, NROWS / 128, 1);
    gemm_fused<<<gproj, 256>>>(nullptr, nullptr, nullptr, Wo, nullptr, nullptr,
                               bo, nullptr, nullptr, 1);
    ln_kernel<<<NROWS, 256>>>(gamma, beta, out);
}